// round 13
// baseline (speedup 1.0000x reference)
#include <cuda_runtime.h>
#include <cuda_fp16.h>
#include <math.h>
#include <stdint.h>

// Problem constants
#define BSZ 16384
#define DD  512
#define KC  1024
#define ALPHA 10.0f
#define BETA  0.25f
#define TAU  1e-3f          // argmax ambiguity threshold (logit units)

// Output layout (concatenated fp32):
//  quantized [B,D], vq_loss [1], entropy_vq [1], argm [B], hard_quantized [B,D],
//  soft_assign [B,K], cluster_metric [1]
// OFF_HQ / OFF_SA are == 2 mod 4 floats -> only 8-byte aligned.
#define OFF_Q   ((size_t)0)
#define OFF_VQ  ((size_t)(BSZ*DD))
#define OFF_ENT (OFF_VQ + 1)
#define OFF_ARG (OFF_ENT + 1)
#define OFF_HQ  (OFF_ARG + BSZ)
#define OFF_SA  (OFF_HQ + (size_t)BSZ*DD)
#define OFF_CM  (OFF_SA + (size_t)BSZ*KC)

// ---------------------------------------------------------------------------
// Scratch (device globals; no allocation allowed).
__device__ float  g_ln [(size_t)BSZ * DD];   // normalized latents fp32
__device__ float  g_cbn[(size_t)KC * DD];    // normalized codebook fp32 (recheck)
__device__ __align__(128) __half g_lnh[(size_t)BSZ * DD];   // ln fp16
__device__ __align__(128) __half g_cbh[(size_t)KC * DD];    // cbn fp16
__device__ __align__(128) __half g_sah[(size_t)BSZ * KC];   // sa fp16
__device__ __align__(128) __half g_wth[(size_t)DD * KC];    // W^T fp16 [D,K]
__device__ float  g_rowmax[BSZ];
__device__ float  g_avg[KC];
__device__ double g_mse_sum;

// ---------------------------------------------------------------------------
// Baseline-PTX helpers (valid on compute_103): cp.async, ldmatrix, mma.sync
__device__ __forceinline__ uint32_t smem_u32(const void* p) {
    return (uint32_t)__cvta_generic_to_shared(p);
}
__device__ __forceinline__ void cp_async16(uint32_t saddr, const void* gaddr) {
    asm volatile("cp.async.cg.shared.global [%0], [%1], 16;"
                 :: "r"(saddr), "l"(gaddr) : "memory");
}
__device__ __forceinline__ void cp_commit() {
    asm volatile("cp.async.commit_group;" ::: "memory");
}
__device__ __forceinline__ void cp_wait0() {
    asm volatile("cp.async.wait_group 0;" ::: "memory");
}
__device__ __forceinline__ void cp_wait1() {
    asm volatile("cp.async.wait_group 1;" ::: "memory");
}
__device__ __forceinline__ void ldsm_x4(uint32_t& r0, uint32_t& r1,
                                        uint32_t& r2, uint32_t& r3, uint32_t a) {
    asm volatile("ldmatrix.sync.aligned.m8n8.x4.shared.b16 {%0,%1,%2,%3}, [%4];"
                 : "=r"(r0), "=r"(r1), "=r"(r2), "=r"(r3) : "r"(a));
}
__device__ __forceinline__ void mma_h(float* c, const uint32_t* a, const uint32_t* b) {
    asm volatile(
        "mma.sync.aligned.m16n8k16.row.col.f32.f16.f16.f32 "
        "{%0,%1,%2,%3}, {%4,%5,%6,%7}, {%8,%9}, {%0,%1,%2,%3};"
        : "+f"(c[0]), "+f"(c[1]), "+f"(c[2]), "+f"(c[3])
        : "r"(a[0]), "r"(a[1]), "r"(a[2]), "r"(a[3]), "r"(b[0]), "r"(b[1]));
}

// ---------------------------------------------------------------------------
__global__ void init_kernel() {
    int t = threadIdx.x;
    if (t < KC) g_avg[t] = 0.0f;
    if (t == 0) g_mse_sum = 0.0;
}

// ---------------------------------------------------------------------------
// Row L2 normalize -> fp32 + fp16. One block (128 thr) per row of 512.
__global__ __launch_bounds__(128) void l2norm_kernel(
    const float* __restrict__ x, float* __restrict__ y, __half* __restrict__ yh)
{
    int r = blockIdx.x;
    int t = threadIdx.x;
    const float4* xr = (const float4*)(x + (size_t)r * DD);
    float4 v = xr[t];
    float s = v.x * v.x + v.y * v.y + v.z * v.z + v.w * v.w;
    #pragma unroll
    for (int o = 16; o > 0; o >>= 1) s += __shfl_xor_sync(0xffffffffu, s, o);
    __shared__ float sm[4];
    if ((t & 31) == 0) sm[t >> 5] = s;
    __syncthreads();
    float tot = sm[0] + sm[1] + sm[2] + sm[3];
    float inv = 1.0f / fmaxf(sqrtf(tot), 1e-12f);
    float o0 = v.x * inv, o1 = v.y * inv, o2 = v.z * inv, o3 = v.w * inv;
    ((float4*)(y + (size_t)r * DD))[t] = make_float4(o0, o1, o2, o3);
    *(__half2*)(yh + (size_t)r * DD + t * 4 + 0) = __floats2half2_rn(o0, o1);
    *(__half2*)(yh + (size_t)r * DD + t * 4 + 2) = __floats2half2_rn(o2, o3);
}

// ---------------------------------------------------------------------------
// W [KC, DD] -> Wt fp16 [DD, KC]
__global__ __launch_bounds__(1024) void transpose_h_kernel(
    const float* __restrict__ W, __half* __restrict__ th)
{
    __shared__ float tile[32][33];
    int k0 = blockIdx.x * 32, d0 = blockIdx.y * 32;
    int tx = threadIdx.x & 31, ty = threadIdx.x >> 5;
    tile[ty][tx] = W[(size_t)(k0 + ty) * DD + d0 + tx];
    __syncthreads();
    float v = tile[tx][ty];
    th[(size_t)(d0 + ty) * KC + k0 + tx] = __float2half_rn(v);
}

// ---------------------------------------------------------------------------
#define ROWB   80            // 64B data + 16B pad per 32-half row

// ===========================================================================
// FUSED GEMM1 + softmax + argmax(+exact recheck) + sa/sah/hardq/colsum/rowmax.
// CTA tile: 32 rows x 1024 cols (full K). 8 warps; warp w owns cols
// [w*128, w*128+128). acc[2][16][4] = 128 fp32/thread. K loop over D=512 in
// BK=32 chunks, double-buffered cp.async (A: 32x32, B: 1024x32 per stage).
// ===========================================================================
#define FM_CTA   32
#define FTHREADS 256
#define F_A_B  (FM_CTA * ROWB)       // 2560
#define F_B_B  (KC * ROWB)           // 81920
#define F_STAGE (F_A_B + F_B_B)      // 84480
#define F_SMEM (2 * F_STAGE)         // 168960

__global__ __launch_bounds__(FTHREADS, 1) void gemm1_softmax_kernel(
    const __half* __restrict__ A,    // lnh [BSZ, DD]
    const __half* __restrict__ Bm,   // cbh [KC, DD]
    const float* __restrict__ W,     // emb [KC, DD]
    const float* __restrict__ ln, const float* __restrict__ cbn,
    float* __restrict__ sa, float* __restrict__ argm_out,
    float* __restrict__ hardq)
{
    extern __shared__ char smraw[];
    __shared__ float s_rm[FM_CTA][8];
    __shared__ int   s_ri[FM_CTA][8];
    __shared__ float s_rs[FM_CTA][8];
    __shared__ float s_rowmax[FM_CTA];
    __shared__ float s_rowinv[FM_CTA];
    __shared__ int   s_rowarg[FM_CTA];
    __shared__ int   s_cnt[FM_CTA];
    __shared__ int   s_cand[FM_CTA][8];
    __shared__ int   s_amb[FM_CTA];
    __shared__ int   s_namb;

    int tid = threadIdx.x;
    int w = tid >> 5, l = tid & 31;
    int bm = blockIdx.x * FM_CTA;
    int wbase = w * 128;

    if (tid < FM_CTA) s_cnt[tid] = 0;
    if (tid == 0) s_namb = 0;

    uint32_t sbase = smem_u32(smraw);
    const __half* Ap = A + (size_t)bm * DD;

    auto load_stage = [&](int kc, int st) {
        uint32_t sb = sbase + st * F_STAGE;
        if (tid < 128) {
            int row = tid >> 2, col = tid & 3;
            cp_async16(sb + row * ROWB + col * 16,
                       (const char*)(Ap + (size_t)row * DD + kc * 32) + col * 16);
        }
        uint32_t bb = sb + F_A_B;
        #pragma unroll
        for (int it = 0; it < 16; it++) {
            int g = it * FTHREADS + tid;
            int row = g >> 2, col = g & 3;
            cp_async16(bb + row * ROWB + col * 16,
                       (const char*)(Bm + (size_t)row * DD + kc * 32) + col * 16);
        }
        cp_commit();
    };

    float acc[2][16][4];
    #pragma unroll
    for (int i = 0; i < 2; i++)
        #pragma unroll
        for (int j = 0; j < 16; j++)
            #pragma unroll
            for (int q = 0; q < 4; q++) acc[i][j][q] = 0.0f;

    load_stage(0, 0);
    const int NCH = DD / 32;
    for (int kc = 0; kc < NCH; kc++) {
        int st = kc & 1;
        if (kc + 1 < NCH) { load_stage(kc + 1, st ^ 1); cp_wait1(); }
        else              { cp_wait0(); }
        __syncthreads();

        uint32_t ab = sbase + st * F_STAGE;
        uint32_t bb = ab + F_A_B;
        int ldrow = l & 15;
        int ldcol = (l >> 4) * 16;

        #pragma unroll
        for (int kk = 0; kk < 2; kk++) {
            int kb = kk * 32 + ldcol;
            uint32_t a_r[2][4];
            #pragma unroll
            for (int mt = 0; mt < 2; mt++) {
                ldsm_x4(a_r[mt][0], a_r[mt][1], a_r[mt][2], a_r[mt][3],
                        ab + (uint32_t)(mt * 16 + ldrow) * ROWB + kb);
            }
            uint32_t b_r[16][2];
            #pragma unroll
            for (int np = 0; np < 8; np++) {
                uint32_t r0, r1, r2, r3;
                ldsm_x4(r0, r1, r2, r3,
                        bb + (uint32_t)(wbase + np * 16 + ldrow) * ROWB + kb);
                b_r[2 * np][0] = r0; b_r[2 * np][1] = r2;
                b_r[2 * np + 1][0] = r1; b_r[2 * np + 1][1] = r3;
            }
            #pragma unroll
            for (int mt = 0; mt < 2; mt++)
                #pragma unroll
                for (int nt = 0; nt < 16; nt++)
                    mma_h(acc[mt][nt], a_r[mt], b_r[nt]);
        }
        __syncthreads();
    }

    // ---- Pass 1: row max + argmax (approx logits) ----
    // lane rows: R[rq] = (l>>2) + rq*8 ; acc value: acc[rq>>1][nt][(rq&1)*2 + j]
    float lm[4]; int li[4];
    #pragma unroll
    for (int rq = 0; rq < 4; rq++) { lm[rq] = -3.4e38f; li[rq] = 0; }
    #pragma unroll
    for (int nt = 0; nt < 16; nt++) {
        int c0 = wbase + nt * 8 + (l & 3) * 2;
        #pragma unroll
        for (int rq = 0; rq < 4; rq++) {
            float x0 = acc[rq >> 1][nt][(rq & 1) * 2];
            float x1 = acc[rq >> 1][nt][(rq & 1) * 2 + 1];
            if (x0 > lm[rq]) { lm[rq] = x0; li[rq] = c0; }
            if (x1 > lm[rq]) { lm[rq] = x1; li[rq] = c0 + 1; }
        }
    }
    #pragma unroll
    for (int o = 1; o <= 2; o <<= 1) {
        #pragma unroll
        for (int rq = 0; rq < 4; rq++) {
            float ov = __shfl_xor_sync(0xffffffffu, lm[rq], o);
            int   oi = __shfl_xor_sync(0xffffffffu, li[rq], o);
            if (ov > lm[rq] || (ov == lm[rq] && oi < li[rq])) { lm[rq] = ov; li[rq] = oi; }
        }
    }
    if ((l & 3) == 0) {
        #pragma unroll
        for (int rq = 0; rq < 4; rq++) {
            s_rm[(l >> 2) + rq * 8][w] = lm[rq];
            s_ri[(l >> 2) + rq * 8][w] = li[rq];
        }
    }
    __syncthreads();
    if (tid < FM_CTA) {
        float bv = -3.4e38f; int bi = 0x7fffffff;
        #pragma unroll
        for (int ww = 0; ww < 8; ww++) {
            float v = s_rm[tid][ww]; int i = s_ri[tid][ww];
            if (v > bv || (v == bv && i < bi)) { bv = v; bi = i; }
        }
        s_rowmax[tid] = bv; s_rowarg[tid] = bi;
    }
    __syncthreads();

    // ---- Pass 2: exp + row sums + candidate collection ----
    float ls[4] = {0.0f, 0.0f, 0.0f, 0.0f};
    float rmx[4];
    #pragma unroll
    for (int rq = 0; rq < 4; rq++) rmx[rq] = s_rowmax[(l >> 2) + rq * 8];
    #pragma unroll
    for (int nt = 0; nt < 16; nt++) {
        int c0 = wbase + nt * 8 + (l & 3) * 2;
        #pragma unroll
        for (int rq = 0; rq < 4; rq++) {
            int row = (l >> 2) + rq * 8;
            float x0 = acc[rq >> 1][nt][(rq & 1) * 2];
            float x1 = acc[rq >> 1][nt][(rq & 1) * 2 + 1];
            if (x0 >= rmx[rq] - TAU) {
                int p = atomicAdd(&s_cnt[row], 1);
                if (p < 8) s_cand[row][p] = c0;
            }
            if (x1 >= rmx[rq] - TAU) {
                int p = atomicAdd(&s_cnt[row], 1);
                if (p < 8) s_cand[row][p] = c0 + 1;
            }
            float e0 = expf(ALPHA * (x0 - rmx[rq]));
            float e1 = expf(ALPHA * (x1 - rmx[rq]));
            acc[rq >> 1][nt][(rq & 1) * 2]     = e0;
            acc[rq >> 1][nt][(rq & 1) * 2 + 1] = e1;
            ls[rq] += e0 + e1;
        }
    }
    #pragma unroll
    for (int o = 1; o <= 2; o <<= 1)
        #pragma unroll
        for (int rq = 0; rq < 4; rq++)
            ls[rq] += __shfl_xor_sync(0xffffffffu, ls[rq], o);
    if ((l & 3) == 0) {
        #pragma unroll
        for (int rq = 0; rq < 4; rq++) s_rs[(l >> 2) + rq * 8][w] = ls[rq];
    }
    __syncthreads();
    if (tid < FM_CTA) {
        float s = 0.0f;
        #pragma unroll
        for (int ww = 0; ww < 8; ww++) s += s_rs[tid][ww];
        s_rowinv[tid] = 1.0f / s;
        int c = s_cnt[tid];
        if (c > 1 && c <= 8) {
            int p = atomicAdd(&s_namb, 1);
            s_amb[p] = tid;
        }
    }
    __syncthreads();

    // ---- Pass 3: exact fp32 recheck of ambiguous rows (one warp per row) ----
    int namb = s_namb;
    for (int i = w; i < namb; i += 8) {
        int row = s_amb[i];
        int cnt = s_cnt[row];
        size_t grow = (size_t)(bm + row);
        float best = -3.4e38f; int bidx = 0x7fffffff;
        const float4* a4 = (const float4*)(ln + grow * DD);
        for (int c = 0; c < cnt; c++) {
            int k = s_cand[row][c];
            const float4* b4 = (const float4*)(cbn + (size_t)k * DD);
            float p = 0.0f;
            #pragma unroll
            for (int it = 0; it < 4; it++) {
                float4 a = a4[it * 32 + l];
                float4 b = b4[it * 32 + l];
                p += a.x * b.x + a.y * b.y + a.z * b.z + a.w * b.w;
            }
            #pragma unroll
            for (int o = 16; o > 0; o >>= 1) p += __shfl_xor_sync(0xffffffffu, p, o);
            if (p > best || (p == best && k < bidx)) { best = p; bidx = k; }
        }
        if (l == 0) s_rowarg[row] = bidx;
    }
    __syncthreads();

    // ---- Pass 4: write sa (fp32 + fp16) and accumulate column partials ----
    float colp[32];
    #pragma unroll
    for (int i = 0; i < 32; i++) colp[i] = 0.0f;
    #pragma unroll
    for (int nt = 0; nt < 16; nt++) {
        int c0 = wbase + nt * 8 + (l & 3) * 2;
        #pragma unroll
        for (int rq = 0; rq < 4; rq++) {
            int row = (l >> 2) + rq * 8;
            float inv = s_rowinv[row];
            float p0 = acc[rq >> 1][nt][(rq & 1) * 2]     * inv;
            float p1 = acc[rq >> 1][nt][(rq & 1) * 2 + 1] * inv;
            size_t gr = (size_t)(bm + row) * KC + c0;
            *(float2*)(sa + gr) = make_float2(p0, p1);
            *(__half2*)(g_sah + gr) = __floats2half2_rn(p0, p1);
            colp[nt * 2]     += p0;
            colp[nt * 2 + 1] += p1;
        }
    }
    #pragma unroll
    for (int o = 4; o <= 16; o <<= 1)
        #pragma unroll
        for (int i = 0; i < 32; i++)
            colp[i] += __shfl_xor_sync(0xffffffffu, colp[i], o);
    if (l < 4) {
        #pragma unroll
        for (int i = 0; i < 32; i++) {
            int col = wbase + (i >> 1) * 8 + (l & 3) * 2 + (i & 1);
            atomicAdd(&g_avg[col], colp[i]);
        }
    }

    // ---- Pass 5: argm/rowmax outputs + hard_quantized ----
    if (tid < FM_CTA) {
        argm_out[bm + tid] = (float)s_rowarg[tid];
        g_rowmax[bm + tid] = s_rowmax[tid];
    }
    int hrow = tid >> 3, hseg = tid & 7;
    int ha = s_rowarg[hrow];
    const float2* wsrc = (const float2*)(W + (size_t)ha * DD) + hseg * 32;
    float2* hdst = (float2*)(hardq + (size_t)(bm + hrow) * DD) + hseg * 32;
    #pragma unroll
    for (int i = 0; i < 32; i++) hdst[i] = wsrc[i];
}

// ---------------------------------------------------------------------------
// HMMA fp16 GEMM (GEMM2), CTA tile 128x128, BK=32, 8 warps, warp tile 64x32.
// C = A * B^T with fused sum((C - Lref)^2) into g_mse_sum.
#define GTHREADS 256
#define TILE_B (128 * ROWB)
#define STAGE_B (2 * TILE_B)
#define GSMEM (2 * STAGE_B)

__global__ __launch_bounds__(GTHREADS, 1) void hmma_gemm2_kernel(
    const __half* __restrict__ A, const __half* __restrict__ B,
    float* __restrict__ C, const float* __restrict__ Lref, int Ntot, int Kd)
{
    extern __shared__ char smraw[];
    int tid = threadIdx.x;
    int w = tid >> 5, l = tid & 31;
    int wm = w & 1, wn = w >> 1;
    int bm = blockIdx.y * 128;
    int bn = blockIdx.x * 128;

    const __half* gtile[2] = { A + (size_t)bm * Kd, B + (size_t)bn * Kd };
    uint32_t sbase = smem_u32(smraw);

    auto load_stage = [&](int kc, int st) {
        uint32_t sb = sbase + st * STAGE_B;
        #pragma unroll
        for (int it = 0; it < 4; it++) {
            int g = it * GTHREADS + tid;
            int tile = g >> 9;
            int c = g & 511;
            int row = c >> 2;
            int col = c & 3;
            const char* src = (const char*)(gtile[tile] + (size_t)row * Kd + kc * 32)
                              + col * 16;
            cp_async16(sb + tile * TILE_B + row * ROWB + col * 16, src);
        }
        cp_commit();
    };

    float acc[4][4][4];
    #pragma unroll
    for (int i = 0; i < 4; i++)
        #pragma unroll
        for (int j = 0; j < 4; j++)
            #pragma unroll
            for (int q = 0; q < 4; q++) acc[i][j][q] = 0.0f;

    int nch = Kd >> 5;
    load_stage(0, 0);

    for (int kc = 0; kc < nch; kc++) {
        int st = kc & 1;
        if (kc + 1 < nch) { load_stage(kc + 1, st ^ 1); cp_wait1(); }
        else              { cp_wait0(); }
        __syncthreads();

        uint32_t ab = sbase + st * STAGE_B;
        uint32_t bb = sbase + st * STAGE_B + TILE_B;
        int ldrow = l & 15;
        int ldcol = (l >> 4) * 16;

        #pragma unroll
        for (int kk = 0; kk < 2; kk++) {
            int kb = kk * 32 + ldcol;
            uint32_t a_r[4][4];
            #pragma unroll
            for (int mt = 0; mt < 4; mt++) {
                uint32_t off = (uint32_t)(wm * 64 + mt * 16 + ldrow) * ROWB + kb;
                ldsm_x4(a_r[mt][0], a_r[mt][1], a_r[mt][2], a_r[mt][3], ab + off);
            }
            uint32_t b_r[4][2];
            #pragma unroll
            for (int np = 0; np < 2; np++) {
                uint32_t off = (uint32_t)(wn * 32 + np * 16 + ldrow) * ROWB + kb;
                uint32_t r0, r1, r2, r3;
                ldsm_x4(r0, r1, r2, r3, bb + off);
                b_r[2 * np][0] = r0; b_r[2 * np][1] = r2;
                b_r[2 * np + 1][0] = r1; b_r[2 * np + 1][1] = r3;
            }
            #pragma unroll
            for (int mt = 0; mt < 4; mt++)
                #pragma unroll
                for (int nt = 0; nt < 4; nt++)
                    mma_h(acc[mt][nt], a_r[mt], b_r[nt]);
        }
        __syncthreads();
    }

    float msum = 0.0f;
    #pragma unroll
    for (int mt = 0; mt < 4; mt++) {
        int r0 = bm + wm * 64 + mt * 16 + (l >> 2);
        #pragma unroll
        for (int nt = 0; nt < 4; nt++) {
            int cb = bn + wn * 32 + nt * 8 + (l & 3) * 2;
            float2 v01 = make_float2(acc[mt][nt][0], acc[mt][nt][1]);
            float2 v23 = make_float2(acc[mt][nt][2], acc[mt][nt][3]);
            *(float2*)(C + (size_t)r0 * Ntot + cb) = v01;
            *(float2*)(C + (size_t)(r0 + 8) * Ntot + cb) = v23;
            float2 l01 = *(const float2*)(Lref + (size_t)r0 * Ntot + cb);
            float2 l23 = *(const float2*)(Lref + (size_t)(r0 + 8) * Ntot + cb);
            float d0 = v01.x - l01.x, d1 = v01.y - l01.y;
            float d2 = v23.x - l23.x, d3 = v23.y - l23.y;
            msum += d0 * d0 + d1 * d1 + d2 * d2 + d3 * d3;
        }
    }
    #pragma unroll
    for (int o = 16; o > 0; o >>= 1)
        msum += __shfl_xor_sync(0xffffffffu, msum, o);
    __shared__ float smm[8];
    if (l == 0) smm[w] = msum;
    __syncthreads();
    if (tid == 0) {
        float tot = 0.0f;
        #pragma unroll
        for (int q = 0; q < 8; q++) tot += smm[q];
        atomicAdd(&g_mse_sum, (double)tot);
    }
}

// ---------------------------------------------------------------------------
// Final scalars: vq_loss (from fused mse), entropy_vq, cluster_metric (rowmax).
__global__ __launch_bounds__(1024) void finalize_kernel(float* __restrict__ out)
{
    int t = threadIdx.x;
    float p = g_avg[t] * (1.0f / (float)BSZ);
    float ent = p * logf(p + 1e-10f);
    float rmx = 0.0f;
    #pragma unroll
    for (int j = 0; j < 16; j++) rmx += g_rowmax[t + j * 1024];
    __shared__ float se[1024];
    __shared__ float sr[1024];
    se[t] = ent; sr[t] = rmx;
    __syncthreads();
    #pragma unroll
    for (int s = 512; s > 0; s >>= 1) {
        if (t < s) { se[t] += se[t + s]; sr[t] += sr[t + s]; }
        __syncthreads();
    }
    if (t == 0) {
        double mse = g_mse_sum / (double)((size_t)BSZ * DD);
        out[OFF_VQ]  = (float)((1.0 + (double)BETA) * mse);
        out[OFF_ENT] = -se[0];
        out[OFF_CM]  = (float)((double)sr[0] / (double)BSZ);
    }
}

// ---------------------------------------------------------------------------
extern "C" void kernel_launch(void* const* d_in, const int* in_sizes, int n_in,
                              void* d_out, int out_size)
{
    const float* latents = (const float*)d_in[0];   // [B, D]
    const float* emb     = (const float*)d_in[1];   // [K, D]
    float* out = (float*)d_out;

    float* ln  = 0; cudaGetSymbolAddress((void**)&ln,  g_ln);
    float* cbn = 0; cudaGetSymbolAddress((void**)&cbn, g_cbn);
    __half *lnh = 0, *cbh = 0, *sah = 0, *wth = 0;
    cudaGetSymbolAddress((void**)&lnh, g_lnh);
    cudaGetSymbolAddress((void**)&cbh, g_cbh);
    cudaGetSymbolAddress((void**)&sah, g_sah);
    cudaGetSymbolAddress((void**)&wth, g_wth);

    cudaFuncSetAttribute((const void*)gemm1_softmax_kernel,
                         cudaFuncAttributeMaxDynamicSharedMemorySize, F_SMEM);
    cudaFuncSetAttribute((const void*)hmma_gemm2_kernel,
                         cudaFuncAttributeMaxDynamicSharedMemorySize, GSMEM);

    float* q_out   = out + OFF_Q;
    float* arg_out = out + OFF_ARG;
    float* hq_out  = out + OFF_HQ;
    float* sa_out  = out + OFF_SA;

    init_kernel<<<1, 1024>>>();
    l2norm_kernel<<<KC, 128>>>(emb, cbn, cbh);
    l2norm_kernel<<<BSZ, 128>>>(latents, ln, lnh);
    {
        dim3 grid(KC / 32, DD / 32);
        transpose_h_kernel<<<grid, 1024>>>(emb, wth);
    }

    // attention + softmax + argmax + sa/sah/hardq/colsum, all fused
    gemm1_softmax_kernel<<<BSZ / FM_CTA, FTHREADS, F_SMEM>>>(
        lnh, cbh, emb, ln, cbn, sa_out, arg_out, hq_out);

    // quantized = sa [B,1024] * Wt [512,1024]^T  (fp16, fp32 acc, fused MSE)
    {
        dim3 grid(DD / 128, BSZ / 128);
        hmma_gemm2_kernel<<<grid, GTHREADS, GSMEM>>>(sah, wth, q_out, ln, DD, KC);
    }

    finalize_kernel<<<1, 1024>>>(out);
}

// round 15
// speedup vs baseline: 1.3486x; 1.3486x over previous
#include <cuda_runtime.h>
#include <cuda_fp16.h>
#include <math.h>
#include <stdint.h>

// Problem constants
#define BSZ 16384
#define DD  512
#define KC  1024
#define ALPHA 10.0f
#define BETA  0.25f
#define TAU  1e-3f          // argmax ambiguity threshold (logit units)

// Output layout (concatenated fp32):
//  quantized [B,D], vq_loss [1], entropy_vq [1], argm [B], hard_quantized [B,D],
//  soft_assign [B,K], cluster_metric [1]
// OFF_HQ / OFF_SA are == 2 mod 4 floats -> only 8-byte aligned.
#define OFF_Q   ((size_t)0)
#define OFF_VQ  ((size_t)(BSZ*DD))
#define OFF_ENT (OFF_VQ + 1)
#define OFF_ARG (OFF_ENT + 1)
#define OFF_HQ  (OFF_ARG + BSZ)
#define OFF_SA  (OFF_HQ + (size_t)BSZ*DD)
#define OFF_CM  (OFF_SA + (size_t)BSZ*KC)

// ---------------------------------------------------------------------------
// Scratch (device globals; no allocation allowed).
__device__ float  g_cbn[(size_t)KC * DD];    // normalized codebook fp32 (recheck)
__device__ __align__(128) __half g_atth[(size_t)BSZ * KC];  // logits fp16
__device__ __align__(128) __half g_lnh[(size_t)BSZ * DD];   // ln fp16
__device__ __align__(128) __half g_cbh[(size_t)KC * DD];    // cbn fp16
__device__ __align__(128) __half g_sah[(size_t)BSZ * KC];   // sa fp16
__device__ __align__(128) __half g_wth[(size_t)DD * KC];    // W^T fp16 [D,K]
__device__ float  g_rowmax[BSZ];
__device__ float  g_avg[KC];
__device__ double g_mse_sum;

// ---------------------------------------------------------------------------
// Baseline-PTX helpers (valid on compute_103): cp.async, ldmatrix, mma.sync
__device__ __forceinline__ uint32_t smem_u32(const void* p) {
    return (uint32_t)__cvta_generic_to_shared(p);
}
__device__ __forceinline__ void cp_async16(uint32_t saddr, const void* gaddr) {
    asm volatile("cp.async.cg.shared.global [%0], [%1], 16;"
                 :: "r"(saddr), "l"(gaddr) : "memory");
}
__device__ __forceinline__ void cp_commit() {
    asm volatile("cp.async.commit_group;" ::: "memory");
}
__device__ __forceinline__ void cp_wait0() {
    asm volatile("cp.async.wait_group 0;" ::: "memory");
}
__device__ __forceinline__ void cp_wait1() {
    asm volatile("cp.async.wait_group 1;" ::: "memory");
}
__device__ __forceinline__ void ldsm_x4(uint32_t& r0, uint32_t& r1,
                                        uint32_t& r2, uint32_t& r3, uint32_t a) {
    asm volatile("ldmatrix.sync.aligned.m8n8.x4.shared.b16 {%0,%1,%2,%3}, [%4];"
                 : "=r"(r0), "=r"(r1), "=r"(r2), "=r"(r3) : "r"(a));
}
__device__ __forceinline__ void mma_h(float* c, const uint32_t* a, const uint32_t* b) {
    asm volatile(
        "mma.sync.aligned.m16n8k16.row.col.f32.f16.f16.f32 "
        "{%0,%1,%2,%3}, {%4,%5,%6,%7}, {%8,%9}, {%0,%1,%2,%3};"
        : "+f"(c[0]), "+f"(c[1]), "+f"(c[2]), "+f"(c[3])
        : "r"(a[0]), "r"(a[1]), "r"(a[2]), "r"(a[3]), "r"(b[0]), "r"(b[1]));
}

// ---------------------------------------------------------------------------
__global__ void init_kernel() {
    int t = threadIdx.x;
    if (t < KC) g_avg[t] = 0.0f;
    if (t == 0) g_mse_sum = 0.0;
}

// ---------------------------------------------------------------------------
// Row L2 normalize. FULL: also write fp32 copy. One block (128 thr) per row.
template <bool FULL>
__global__ __launch_bounds__(128) void l2norm_kernel(
    const float* __restrict__ x, float* __restrict__ y, __half* __restrict__ yh)
{
    int r = blockIdx.x;
    int t = threadIdx.x;
    const float4* xr = (const float4*)(x + (size_t)r * DD);
    float4 v = xr[t];
    float s = v.x * v.x + v.y * v.y + v.z * v.z + v.w * v.w;
    #pragma unroll
    for (int o = 16; o > 0; o >>= 1) s += __shfl_xor_sync(0xffffffffu, s, o);
    __shared__ float sm[4];
    if ((t & 31) == 0) sm[t >> 5] = s;
    __syncthreads();
    float tot = sm[0] + sm[1] + sm[2] + sm[3];
    float inv = 1.0f / fmaxf(sqrtf(tot), 1e-12f);
    float o0 = v.x * inv, o1 = v.y * inv, o2 = v.z * inv, o3 = v.w * inv;
    if (FULL) ((float4*)(y + (size_t)r * DD))[t] = make_float4(o0, o1, o2, o3);
    *(__half2*)(yh + (size_t)r * DD + t * 4 + 0) = __floats2half2_rn(o0, o1);
    *(__half2*)(yh + (size_t)r * DD + t * 4 + 2) = __floats2half2_rn(o2, o3);
}

// ---------------------------------------------------------------------------
// W [KC, DD] -> Wt fp16 [DD, KC]
__global__ __launch_bounds__(1024) void transpose_h_kernel(
    const float* __restrict__ W, __half* __restrict__ th)
{
    __shared__ float tile[32][33];
    int k0 = blockIdx.x * 32, d0 = blockIdx.y * 32;
    int tx = threadIdx.x & 31, ty = threadIdx.x >> 5;
    tile[ty][tx] = W[(size_t)(k0 + ty) * DD + d0 + tx];
    __syncthreads();
    float v = tile[tx][ty];
    th[(size_t)(d0 + ty) * KC + k0 + tx] = __float2half_rn(v);
}

// ---------------------------------------------------------------------------
// HMMA fp16 GEMM, CTA tile 128x128, BK=32, 8 warps (2Mx4N), warp tile 64x32.
// C[M,N] = A[M,Kd] * B[N,Kd]^T  (fp32 accum)
// HOUT: write C as fp16.  FUSE: accumulate sum((C - Lref16)^2) into g_mse_sum.
#define GTHREADS 256
#define ROWB   80
#define TILE_B (128 * ROWB)
#define STAGE_B (2 * TILE_B)
#define GSMEM (2 * STAGE_B)          // 40960

template<bool HOUT, bool FUSE>
__global__ __launch_bounds__(GTHREADS, 1) void hmma_gemm_kernel(
    const __half* __restrict__ A, const __half* __restrict__ B,
    void* __restrict__ Cv, const __half* __restrict__ Lref, int Ntot, int Kd)
{
    extern __shared__ char smraw[];
    int tid = threadIdx.x;
    int w = tid >> 5, l = tid & 31;
    int wm = w & 1, wn = w >> 1;
    int bm = blockIdx.y * 128;
    int bn = blockIdx.x * 128;

    const __half* gtile[2] = { A + (size_t)bm * Kd, B + (size_t)bn * Kd };
    uint32_t sbase = smem_u32(smraw);

    auto load_stage = [&](int kc, int st) {
        uint32_t sb = sbase + st * STAGE_B;
        #pragma unroll
        for (int it = 0; it < 4; it++) {
            int g = it * GTHREADS + tid;
            int tile = g >> 9;
            int c = g & 511;
            int row = c >> 2;
            int col = c & 3;
            const char* src = (const char*)(gtile[tile] + (size_t)row * Kd + kc * 32)
                              + col * 16;
            cp_async16(sb + tile * TILE_B + row * ROWB + col * 16, src);
        }
        cp_commit();
    };

    float acc[4][4][4];
    #pragma unroll
    for (int i = 0; i < 4; i++)
        #pragma unroll
        for (int j = 0; j < 4; j++)
            #pragma unroll
            for (int q = 0; q < 4; q++) acc[i][j][q] = 0.0f;

    int nch = Kd >> 5;
    load_stage(0, 0);

    for (int kc = 0; kc < nch; kc++) {
        int st = kc & 1;
        if (kc + 1 < nch) { load_stage(kc + 1, st ^ 1); cp_wait1(); }
        else              { cp_wait0(); }
        __syncthreads();

        uint32_t ab = sbase + st * STAGE_B;
        uint32_t bb = sbase + st * STAGE_B + TILE_B;
        int ldrow = l & 15;
        int ldcol = (l >> 4) * 16;

        #pragma unroll
        for (int kk = 0; kk < 2; kk++) {
            int kb = kk * 32 + ldcol;
            uint32_t a_r[4][4];
            #pragma unroll
            for (int mt = 0; mt < 4; mt++) {
                uint32_t off = (uint32_t)(wm * 64 + mt * 16 + ldrow) * ROWB + kb;
                ldsm_x4(a_r[mt][0], a_r[mt][1], a_r[mt][2], a_r[mt][3], ab + off);
            }
            uint32_t b_r[4][2];
            #pragma unroll
            for (int np = 0; np < 2; np++) {
                uint32_t off = (uint32_t)(wn * 32 + np * 16 + ldrow) * ROWB + kb;
                uint32_t r0, r1, r2, r3;
                ldsm_x4(r0, r1, r2, r3, bb + off);
                b_r[2 * np][0] = r0; b_r[2 * np][1] = r2;
                b_r[2 * np + 1][0] = r1; b_r[2 * np + 1][1] = r3;
            }
            #pragma unroll
            for (int mt = 0; mt < 4; mt++)
                #pragma unroll
                for (int nt = 0; nt < 4; nt++)
                    mma_h(acc[mt][nt], a_r[mt], b_r[nt]);
        }
        __syncthreads();
    }

    // Epilogue
    float msum = 0.0f;
    #pragma unroll
    for (int mt = 0; mt < 4; mt++) {
        int r0 = bm + wm * 64 + mt * 16 + (l >> 2);
        #pragma unroll
        for (int nt = 0; nt < 4; nt++) {
            int cb = bn + wn * 32 + nt * 8 + (l & 3) * 2;
            float a0 = acc[mt][nt][0], a1 = acc[mt][nt][1];
            float a2 = acc[mt][nt][2], a3 = acc[mt][nt][3];
            if constexpr (HOUT) {
                __half* C = (__half*)Cv;
                *(__half2*)(C + (size_t)r0 * Ntot + cb)       = __floats2half2_rn(a0, a1);
                *(__half2*)(C + (size_t)(r0 + 8) * Ntot + cb) = __floats2half2_rn(a2, a3);
            } else {
                float* C = (float*)Cv;
                *(float2*)(C + (size_t)r0 * Ntot + cb)       = make_float2(a0, a1);
                *(float2*)(C + (size_t)(r0 + 8) * Ntot + cb) = make_float2(a2, a3);
            }
            if constexpr (FUSE) {
                float2 l01 = __half22float2(*(const __half2*)(Lref + (size_t)r0 * Ntot + cb));
                float2 l23 = __half22float2(*(const __half2*)(Lref + (size_t)(r0 + 8) * Ntot + cb));
                float d0 = a0 - l01.x, d1 = a1 - l01.y;
                float d2 = a2 - l23.x, d3 = a3 - l23.y;
                msum += d0 * d0 + d1 * d1 + d2 * d2 + d3 * d3;
            }
        }
    }
    if constexpr (FUSE) {
        #pragma unroll
        for (int o = 16; o > 0; o >>= 1)
            msum += __shfl_xor_sync(0xffffffffu, msum, o);
        __shared__ float smm[8];
        if (l == 0) smm[w] = msum;
        __syncthreads();
        if (tid == 0) {
            float tot = 0.0f;
            #pragma unroll
            for (int q = 0; q < 8; q++) tot += smm[q];
            atomicAdd(&g_mse_sum, (double)tot);
        }
    }
}

// ---------------------------------------------------------------------------
// Per-row softmax(ALPHA*att) + exact-rechecked argmax + hard_quantized + fp16 sa.
// att is fp16 (common-mode x_max rounding cancels in softmax). Candidates
// within TAU of rowmax get an exact fp32 dot (latents row renormalized on the
// fly x cbn). sa/hardq live in d_out -> only 8B-aligned: float2 accesses.
__global__ __launch_bounds__(128) void softmax_kernel(
    const __half* __restrict__ att, const float* __restrict__ W,
    const float* __restrict__ latents, const float* __restrict__ cbn,
    float* __restrict__ sa, float* __restrict__ argm_out,
    float* __restrict__ hardq)
{
    int row = blockIdx.x;
    int t = threadIdx.x;

    // 8 contiguous logits per thread (one 16B load)
    uint4 u = ((const uint4*)(att + (size_t)row * KC))[t];
    float v[8];
    {
        float2 f0 = __half22float2(*(__half2*)&u.x);
        float2 f1 = __half22float2(*(__half2*)&u.y);
        float2 f2 = __half22float2(*(__half2*)&u.z);
        float2 f3 = __half22float2(*(__half2*)&u.w);
        v[0] = f0.x; v[1] = f0.y; v[2] = f1.x; v[3] = f1.y;
        v[4] = f2.x; v[5] = f2.y; v[6] = f3.x; v[7] = f3.y;
    }

    float m = -3.4e38f;
    int mi = 0;
    #pragma unroll
    for (int j = 0; j < 8; j++) {
        if (v[j] > m) { m = v[j]; mi = t * 8 + j; }
    }

    __shared__ float smx[128];
    __shared__ int   si[128];
    smx[t] = m; si[t] = mi;
    __syncthreads();
    #pragma unroll
    for (int s = 64; s > 0; s >>= 1) {
        if (t < s) {
            float o = smx[t + s]; int oi = si[t + s];
            if (o > smx[t] || (o == smx[t] && oi < si[t])) { smx[t] = o; si[t] = oi; }
        }
        __syncthreads();
    }
    float rowmax = smx[0];
    int arg = si[0];
    __syncthreads();

    // ---- exact argmax recheck for ambiguous rows ----
    __shared__ int s_cnt;
    __shared__ int s_cand[32];
    __shared__ int s_arg;
    __shared__ float s_red[4];
    __shared__ __align__(16) float s_lnrow[DD];
    if (t == 0) s_cnt = 0;
    __syncthreads();
    #pragma unroll
    for (int j = 0; j < 8; j++) {
        if (v[j] >= rowmax - TAU) {
            int pos = atomicAdd(&s_cnt, 1);
            if (pos < 32) s_cand[pos] = t * 8 + j;
        }
    }
    __syncthreads();
    int cnt = s_cnt;
    if (cnt > 1 && cnt <= 32) {
        // renormalize latents row (fp32) into smem
        float4 a = ((const float4*)(latents + (size_t)row * DD))[t];
        float ss = a.x * a.x + a.y * a.y + a.z * a.z + a.w * a.w;
        #pragma unroll
        for (int o = 16; o > 0; o >>= 1) ss += __shfl_xor_sync(0xffffffffu, ss, o);
        if ((t & 31) == 0) s_red[t >> 5] = ss;
        __syncthreads();
        float inv = 1.0f / fmaxf(sqrtf(s_red[0] + s_red[1] + s_red[2] + s_red[3]), 1e-12f);
        ((float4*)s_lnrow)[t] = make_float4(a.x * inv, a.y * inv, a.z * inv, a.w * inv);
        __syncthreads();

        float bestv = -3.4e38f;
        int besti = 0x7fffffff;
        for (int c = 0; c < cnt; c++) {
            int k = s_cand[c];
            float4 la = ((float4*)s_lnrow)[t];
            float4 b = ((const float4*)(cbn + (size_t)k * DD))[t];
            float p = la.x * b.x + la.y * b.y + la.z * b.z + la.w * b.w;
            #pragma unroll
            for (int o = 16; o > 0; o >>= 1) p += __shfl_xor_sync(0xffffffffu, p, o);
            if ((t & 31) == 0) s_red[t >> 5] = p;
            __syncthreads();
            if (t == 0) {
                float d = s_red[0] + s_red[1] + s_red[2] + s_red[3];
                if (d > bestv || (d == bestv && k < besti)) { bestv = d; besti = k; }
            }
            __syncthreads();
        }
        if (t == 0) s_arg = besti;
        __syncthreads();
        arg = s_arg;
    }

    float lsum = 0.0f;
    #pragma unroll
    for (int j = 0; j < 8; j++) {
        v[j] = expf(ALPHA * (v[j] - rowmax));
        lsum += v[j];
    }
    smx[t] = lsum;
    __syncthreads();
    #pragma unroll
    for (int s = 64; s > 0; s >>= 1) {
        if (t < s) smx[t] += smx[t + s];
        __syncthreads();
    }
    float inv = 1.0f / smx[0];

    size_t rb = (size_t)row * KC + t * 8;
    float p0 = v[0] * inv, p1 = v[1] * inv, p2 = v[2] * inv, p3 = v[3] * inv;
    float p4 = v[4] * inv, p5 = v[5] * inv, p6 = v[6] * inv, p7 = v[7] * inv;
    float* sr = sa + rb;
    *(float2*)(sr + 0) = make_float2(p0, p1);
    *(float2*)(sr + 2) = make_float2(p2, p3);
    *(float2*)(sr + 4) = make_float2(p4, p5);
    *(float2*)(sr + 6) = make_float2(p6, p7);
    uint4 hu;
    *(__half2*)&hu.x = __floats2half2_rn(p0, p1);
    *(__half2*)&hu.y = __floats2half2_rn(p2, p3);
    *(__half2*)&hu.z = __floats2half2_rn(p4, p5);
    *(__half2*)&hu.w = __floats2half2_rn(p6, p7);
    ((uint4*)(g_sah + rb))[0] = hu;

    if (t == 0) {
        argm_out[row] = (float)arg;
        g_rowmax[row] = rowmax;
    }
    // hard_quantized[row,:] = W[arg,:]  (8B-aligned -> float2)
    const float2* wr = (const float2*)(W + (size_t)arg * DD);
    float2* hq = (float2*)(hardq + (size_t)row * DD);
    hq[2 * t + 0] = wr[2 * t + 0];
    hq[2 * t + 1] = wr[2 * t + 1];
}

// ---------------------------------------------------------------------------
// Column sums of soft_assign (reads fp16 copy). grid (KC/256, BSZ/1024).
__global__ __launch_bounds__(256) void colsum_kernel()
{
    int k = blockIdx.x * 256 + threadIdx.x;
    int r0 = blockIdx.y * 1024;
    float s = 0.0f;
    for (int r = 0; r < 1024; r++)
        s += __half2float(g_sah[(size_t)(r0 + r) * KC + k]);
    atomicAdd(&g_avg[k], s);
}

// ---------------------------------------------------------------------------
// Final scalars: vq_loss (from fused mse), entropy_vq, cluster_metric (rowmax).
__global__ __launch_bounds__(1024) void finalize_kernel(float* __restrict__ out)
{
    int t = threadIdx.x;
    float p = g_avg[t] * (1.0f / (float)BSZ);
    float ent = p * logf(p + 1e-10f);
    float rmx = 0.0f;
    #pragma unroll
    for (int j = 0; j < 16; j++) rmx += g_rowmax[t + j * 1024];
    __shared__ float se[1024];
    __shared__ float sr[1024];
    se[t] = ent; sr[t] = rmx;
    __syncthreads();
    #pragma unroll
    for (int s = 512; s > 0; s >>= 1) {
        if (t < s) { se[t] += se[t + s]; sr[t] += sr[t + s]; }
        __syncthreads();
    }
    if (t == 0) {
        double mse = g_mse_sum / (double)((size_t)BSZ * DD);
        out[OFF_VQ]  = (float)((1.0 + (double)BETA) * mse);
        out[OFF_ENT] = -se[0];
        out[OFF_CM]  = (float)((double)sr[0] / (double)BSZ);
    }
}

// ---------------------------------------------------------------------------
extern "C" void kernel_launch(void* const* d_in, const int* in_sizes, int n_in,
                              void* d_out, int out_size)
{
    const float* latents = (const float*)d_in[0];   // [B, D]
    const float* emb     = (const float*)d_in[1];   // [K, D]
    float* out = (float*)d_out;

    float* cbn = 0; cudaGetSymbolAddress((void**)&cbn, g_cbn);
    __half *atth = 0, *lnh = 0, *cbh = 0, *sah = 0, *wth = 0;
    cudaGetSymbolAddress((void**)&atth, g_atth);
    cudaGetSymbolAddress((void**)&lnh, g_lnh);
    cudaGetSymbolAddress((void**)&cbh, g_cbh);
    cudaGetSymbolAddress((void**)&sah, g_sah);
    cudaGetSymbolAddress((void**)&wth, g_wth);

    cudaFuncSetAttribute((const void*)hmma_gemm_kernel<true, false>,
                         cudaFuncAttributeMaxDynamicSharedMemorySize, GSMEM);
    cudaFuncSetAttribute((const void*)hmma_gemm_kernel<false, true>,
                         cudaFuncAttributeMaxDynamicSharedMemorySize, GSMEM);

    float* q_out   = out + OFF_Q;
    float* arg_out = out + OFF_ARG;
    float* hq_out  = out + OFF_HQ;
    float* sa_out  = out + OFF_SA;

    init_kernel<<<1, 1024>>>();
    l2norm_kernel<true><<<KC, 128>>>(emb, cbn, cbh);
    l2norm_kernel<false><<<BSZ, 128>>>(latents, 0, lnh);
    {
        dim3 grid(KC / 32, DD / 32);
        transpose_h_kernel<<<grid, 1024>>>(emb, wth);
    }

    // attention = ln [B,512] * cbn [1024,512]^T  (fp16 in/out, fp32 acc)
    {
        dim3 grid(KC / 128, BSZ / 128);
        hmma_gemm_kernel<true, false><<<grid, GTHREADS, GSMEM>>>(
            lnh, cbh, atth, 0, KC, DD);
    }

    softmax_kernel<<<BSZ, 128>>>(atth, emb, latents, cbn, sa_out, arg_out, hq_out);
    {
        dim3 grid(KC / 256, BSZ / 1024);
        colsum_kernel<<<grid, 256>>>();
    }

    // quantized = sa [B,1024] * Wt [512,1024]^T  (fp16, fp32 acc, fused MSE vs lnh)
    {
        dim3 grid(DD / 128, BSZ / 128);
        hmma_gemm_kernel<false, true><<<grid, GTHREADS, GSMEM>>>(
            sah, wth, q_out, lnh, DD, KC);
    }

    finalize_kernel<<<1, 1024>>>(out);
}

// round 17
// speedup vs baseline: 1.6108x; 1.1944x over previous
#include <cuda_runtime.h>
#include <cuda_fp16.h>
#include <math.h>
#include <stdint.h>

// Problem constants
#define BSZ 16384
#define DD  512
#define KC  1024
#define ALPHA 10.0f
#define BETA  0.25f
#define TAU  1e-3f          // argmax ambiguity threshold (logit units)

// Output layout (concatenated fp32):
//  quantized [B,D], vq_loss [1], entropy_vq [1], argm [B], hard_quantized [B,D],
//  soft_assign [B,K], cluster_metric [1]
// OFF_HQ / OFF_SA are == 2 mod 4 floats -> only 8-byte aligned.
#define OFF_Q   ((size_t)0)
#define OFF_VQ  ((size_t)(BSZ*DD))
#define OFF_ENT (OFF_VQ + 1)
#define OFF_ARG (OFF_ENT + 1)
#define OFF_HQ  (OFF_ARG + BSZ)
#define OFF_SA  (OFF_HQ + (size_t)BSZ*DD)
#define OFF_CM  (OFF_SA + (size_t)BSZ*KC)

// ---------------------------------------------------------------------------
// Scratch (device globals; no allocation allowed).
__device__ float  g_cbn[(size_t)KC * DD];    // normalized codebook fp32 (recheck)
__device__ __align__(128) __half g_atth[(size_t)BSZ * KC];  // logits fp16
__device__ __align__(128) __half g_lnh[(size_t)BSZ * DD];   // ln fp16
__device__ __align__(128) __half g_cbh[(size_t)KC * DD];    // cbn fp16
__device__ __align__(128) __half g_sah[(size_t)BSZ * KC];   // sa fp16
__device__ __align__(128) __half g_wth[(size_t)DD * KC];    // W^T fp16 [D,K]
__device__ float  g_rowmax[BSZ];
__device__ float  g_avg[KC];
__device__ double g_mse_sum;

// ---------------------------------------------------------------------------
// Baseline-PTX helpers (valid on compute_103): cp.async, ldmatrix, mma.sync
__device__ __forceinline__ uint32_t smem_u32(const void* p) {
    return (uint32_t)__cvta_generic_to_shared(p);
}
__device__ __forceinline__ void cp_async16(uint32_t saddr, const void* gaddr) {
    asm volatile("cp.async.cg.shared.global [%0], [%1], 16;"
                 :: "r"(saddr), "l"(gaddr) : "memory");
}
__device__ __forceinline__ void cp_commit() {
    asm volatile("cp.async.commit_group;" ::: "memory");
}
__device__ __forceinline__ void cp_wait0() {
    asm volatile("cp.async.wait_group 0;" ::: "memory");
}
__device__ __forceinline__ void cp_wait1() {
    asm volatile("cp.async.wait_group 1;" ::: "memory");
}
__device__ __forceinline__ void ldsm_x4(uint32_t& r0, uint32_t& r1,
                                        uint32_t& r2, uint32_t& r3, uint32_t a) {
    asm volatile("ldmatrix.sync.aligned.m8n8.x4.shared.b16 {%0,%1,%2,%3}, [%4];"
                 : "=r"(r0), "=r"(r1), "=r"(r2), "=r"(r3) : "r"(a));
}
__device__ __forceinline__ void mma_h(float* c, const uint32_t* a, const uint32_t* b) {
    asm volatile(
        "mma.sync.aligned.m16n8k16.row.col.f32.f16.f16.f32 "
        "{%0,%1,%2,%3}, {%4,%5,%6,%7}, {%8,%9}, {%0,%1,%2,%3};"
        : "+f"(c[0]), "+f"(c[1]), "+f"(c[2]), "+f"(c[3])
        : "r"(a[0]), "r"(a[1]), "r"(a[2]), "r"(a[3]), "r"(b[0]), "r"(b[1]));
}

// ---------------------------------------------------------------------------
__global__ void init_kernel() {
    int t = threadIdx.x;
    if (t < KC) g_avg[t] = 0.0f;
    if (t == 0) g_mse_sum = 0.0;
}

// ---------------------------------------------------------------------------
// Row L2 normalize. FULL: also write fp32 copy. One block (128 thr) per row.
template <bool FULL>
__global__ __launch_bounds__(128) void l2norm_kernel(
    const float* __restrict__ x, float* __restrict__ y, __half* __restrict__ yh)
{
    int r = blockIdx.x;
    int t = threadIdx.x;
    const float4* xr = (const float4*)(x + (size_t)r * DD);
    float4 v = xr[t];
    float s = v.x * v.x + v.y * v.y + v.z * v.z + v.w * v.w;
    #pragma unroll
    for (int o = 16; o > 0; o >>= 1) s += __shfl_xor_sync(0xffffffffu, s, o);
    __shared__ float sm[4];
    if ((t & 31) == 0) sm[t >> 5] = s;
    __syncthreads();
    float tot = sm[0] + sm[1] + sm[2] + sm[3];
    float inv = 1.0f / fmaxf(sqrtf(tot), 1e-12f);
    float o0 = v.x * inv, o1 = v.y * inv, o2 = v.z * inv, o3 = v.w * inv;
    if (FULL) ((float4*)(y + (size_t)r * DD))[t] = make_float4(o0, o1, o2, o3);
    *(__half2*)(yh + (size_t)r * DD + t * 4 + 0) = __floats2half2_rn(o0, o1);
    *(__half2*)(yh + (size_t)r * DD + t * 4 + 2) = __floats2half2_rn(o2, o3);
}

// ---------------------------------------------------------------------------
// W [KC, DD] -> Wt fp16 [DD, KC]
__global__ __launch_bounds__(1024) void transpose_h_kernel(
    const float* __restrict__ W, __half* __restrict__ th)
{
    __shared__ float tile[32][33];
    int k0 = blockIdx.x * 32, d0 = blockIdx.y * 32;
    int tx = threadIdx.x & 31, ty = threadIdx.x >> 5;
    tile[ty][tx] = W[(size_t)(k0 + ty) * DD + d0 + tx];
    __syncthreads();
    float v = tile[tx][ty];
    th[(size_t)(d0 + ty) * KC + k0 + tx] = __float2half_rn(v);
}

// ---------------------------------------------------------------------------
// HMMA fp16 GEMM, CTA tile 128x128, BK=32, 8 warps (2Mx4N), warp tile 64x32.
// C[M,N] = A[M,Kd] * B[N,Kd]^T  (fp32 accum)
// HOUT: write C as fp16.  FUSE: accumulate sum((C - Lref16)^2) into g_mse_sum.
#define GTHREADS 256
#define ROWB   80
#define TILE_B (128 * ROWB)
#define STAGE_B (2 * TILE_B)
#define GSMEM (2 * STAGE_B)          // 40960

template<bool HOUT, bool FUSE>
__global__ __launch_bounds__(GTHREADS, 1) void hmma_gemm_kernel(
    const __half* __restrict__ A, const __half* __restrict__ B,
    void* __restrict__ Cv, const __half* __restrict__ Lref, int Ntot, int Kd)
{
    extern __shared__ char smraw[];
    int tid = threadIdx.x;
    int w = tid >> 5, l = tid & 31;
    int wm = w & 1, wn = w >> 1;
    int bm = blockIdx.y * 128;
    int bn = blockIdx.x * 128;

    const __half* gtile[2] = { A + (size_t)bm * Kd, B + (size_t)bn * Kd };
    uint32_t sbase = smem_u32(smraw);

    auto load_stage = [&](int kc, int st) {
        uint32_t sb = sbase + st * STAGE_B;
        #pragma unroll
        for (int it = 0; it < 4; it++) {
            int g = it * GTHREADS + tid;
            int tile = g >> 9;
            int c = g & 511;
            int row = c >> 2;
            int col = c & 3;
            const char* src = (const char*)(gtile[tile] + (size_t)row * Kd + kc * 32)
                              + col * 16;
            cp_async16(sb + tile * TILE_B + row * ROWB + col * 16, src);
        }
        cp_commit();
    };

    float acc[4][4][4];
    #pragma unroll
    for (int i = 0; i < 4; i++)
        #pragma unroll
        for (int j = 0; j < 4; j++)
            #pragma unroll
            for (int q = 0; q < 4; q++) acc[i][j][q] = 0.0f;

    int nch = Kd >> 5;
    load_stage(0, 0);

    for (int kc = 0; kc < nch; kc++) {
        int st = kc & 1;
        if (kc + 1 < nch) { load_stage(kc + 1, st ^ 1); cp_wait1(); }
        else              { cp_wait0(); }
        __syncthreads();

        uint32_t ab = sbase + st * STAGE_B;
        uint32_t bb = sbase + st * STAGE_B + TILE_B;
        int ldrow = l & 15;
        int ldcol = (l >> 4) * 16;

        #pragma unroll
        for (int kk = 0; kk < 2; kk++) {
            int kb = kk * 32 + ldcol;
            uint32_t a_r[4][4];
            #pragma unroll
            for (int mt = 0; mt < 4; mt++) {
                uint32_t off = (uint32_t)(wm * 64 + mt * 16 + ldrow) * ROWB + kb;
                ldsm_x4(a_r[mt][0], a_r[mt][1], a_r[mt][2], a_r[mt][3], ab + off);
            }
            uint32_t b_r[4][2];
            #pragma unroll
            for (int np = 0; np < 2; np++) {
                uint32_t off = (uint32_t)(wn * 32 + np * 16 + ldrow) * ROWB + kb;
                uint32_t r0, r1, r2, r3;
                ldsm_x4(r0, r1, r2, r3, bb + off);
                b_r[2 * np][0] = r0; b_r[2 * np][1] = r2;
                b_r[2 * np + 1][0] = r1; b_r[2 * np + 1][1] = r3;
            }
            #pragma unroll
            for (int mt = 0; mt < 4; mt++)
                #pragma unroll
                for (int nt = 0; nt < 4; nt++)
                    mma_h(acc[mt][nt], a_r[mt], b_r[nt]);
        }
        __syncthreads();
    }

    // Epilogue
    float msum = 0.0f;
    #pragma unroll
    for (int mt = 0; mt < 4; mt++) {
        int r0 = bm + wm * 64 + mt * 16 + (l >> 2);
        #pragma unroll
        for (int nt = 0; nt < 4; nt++) {
            int cb = bn + wn * 32 + nt * 8 + (l & 3) * 2;
            float a0 = acc[mt][nt][0], a1 = acc[mt][nt][1];
            float a2 = acc[mt][nt][2], a3 = acc[mt][nt][3];
            if constexpr (HOUT) {
                __half* C = (__half*)Cv;
                *(__half2*)(C + (size_t)r0 * Ntot + cb)       = __floats2half2_rn(a0, a1);
                *(__half2*)(C + (size_t)(r0 + 8) * Ntot + cb) = __floats2half2_rn(a2, a3);
            } else {
                float* C = (float*)Cv;
                *(float2*)(C + (size_t)r0 * Ntot + cb)       = make_float2(a0, a1);
                *(float2*)(C + (size_t)(r0 + 8) * Ntot + cb) = make_float2(a2, a3);
            }
            if constexpr (FUSE) {
                float2 l01 = __half22float2(*(const __half2*)(Lref + (size_t)r0 * Ntot + cb));
                float2 l23 = __half22float2(*(const __half2*)(Lref + (size_t)(r0 + 8) * Ntot + cb));
                float d0 = a0 - l01.x, d1 = a1 - l01.y;
                float d2 = a2 - l23.x, d3 = a3 - l23.y;
                msum += d0 * d0 + d1 * d1 + d2 * d2 + d3 * d3;
            }
        }
    }
    if constexpr (FUSE) {
        #pragma unroll
        for (int o = 16; o > 0; o >>= 1)
            msum += __shfl_xor_sync(0xffffffffu, msum, o);
        __shared__ float smm[8];
        if (l == 0) smm[w] = msum;
        __syncthreads();
        if (tid == 0) {
            float tot = 0.0f;
            #pragma unroll
            for (int q = 0; q < 8; q++) tot += smm[q];
            atomicAdd(&g_mse_sum, (double)tot);
        }
    }
}

// ---------------------------------------------------------------------------
// Per-row softmax(ALPHA*att) + exact-rechecked argmax + hard_quantized + fp16 sa.
// att is fp16. Reductions: warp shfl + 4-word smem combine (1 barrier each).
// sa/hardq live in d_out -> only 8B-aligned: float2 accesses.
__global__ __launch_bounds__(128) void softmax_kernel(
    const __half* __restrict__ att, const float* __restrict__ W,
    const float* __restrict__ latents, const float* __restrict__ cbn,
    float* __restrict__ sa, float* __restrict__ argm_out,
    float* __restrict__ hardq)
{
    int row = blockIdx.x;
    int t = threadIdx.x;

    // 8 contiguous logits per thread (one 16B load)
    uint4 u = ((const uint4*)(att + (size_t)row * KC))[t];
    float v[8];
    {
        float2 f0 = __half22float2(*(__half2*)&u.x);
        float2 f1 = __half22float2(*(__half2*)&u.y);
        float2 f2 = __half22float2(*(__half2*)&u.z);
        float2 f3 = __half22float2(*(__half2*)&u.w);
        v[0] = f0.x; v[1] = f0.y; v[2] = f1.x; v[3] = f1.y;
        v[4] = f2.x; v[5] = f2.y; v[6] = f3.x; v[7] = f3.y;
    }

    float m = -3.4e38f;
    int mi = 0;
    #pragma unroll
    for (int j = 0; j < 8; j++) {
        if (v[j] > m) { m = v[j]; mi = t * 8 + j; }
    }
    // warp shfl argmax reduce
    #pragma unroll
    for (int o = 16; o > 0; o >>= 1) {
        float ov = __shfl_xor_sync(0xffffffffu, m, o);
        int   oi = __shfl_xor_sync(0xffffffffu, mi, o);
        if (ov > m || (ov == m && oi < mi)) { m = ov; mi = oi; }
    }
    __shared__ float swm[4];
    __shared__ int   swi[4];
    if ((t & 31) == 0) { swm[t >> 5] = m; swi[t >> 5] = mi; }
    __syncthreads();
    float rowmax; int arg;
    {
        float bv = swm[0]; int bi = swi[0];
        #pragma unroll
        for (int ww = 1; ww < 4; ww++) {
            float vv = swm[ww]; int ii = swi[ww];
            if (vv > bv || (vv == bv && ii < bi)) { bv = vv; bi = ii; }
        }
        rowmax = bv; arg = bi;
    }

    // ---- exact argmax recheck for ambiguous rows ----
    __shared__ int s_cnt;
    __shared__ int s_cand[32];
    __shared__ int s_arg;
    __shared__ float s_red[4];
    __shared__ __align__(16) float s_lnrow[DD];
    if (t == 0) s_cnt = 0;
    __syncthreads();
    #pragma unroll
    for (int j = 0; j < 8; j++) {
        if (v[j] >= rowmax - TAU) {
            int pos = atomicAdd(&s_cnt, 1);
            if (pos < 32) s_cand[pos] = t * 8 + j;
        }
    }
    __syncthreads();
    int cnt = s_cnt;
    if (cnt > 1 && cnt <= 32) {
        // renormalize latents row (fp32) into smem
        float4 a = ((const float4*)(latents + (size_t)row * DD))[t];
        float ss = a.x * a.x + a.y * a.y + a.z * a.z + a.w * a.w;
        #pragma unroll
        for (int o = 16; o > 0; o >>= 1) ss += __shfl_xor_sync(0xffffffffu, ss, o);
        if ((t & 31) == 0) s_red[t >> 5] = ss;
        __syncthreads();
        float inv = 1.0f / fmaxf(sqrtf(s_red[0] + s_red[1] + s_red[2] + s_red[3]), 1e-12f);
        ((float4*)s_lnrow)[t] = make_float4(a.x * inv, a.y * inv, a.z * inv, a.w * inv);
        __syncthreads();

        float bestv = -3.4e38f;
        int besti = 0x7fffffff;
        for (int c = 0; c < cnt; c++) {
            int k = s_cand[c];
            float4 la = ((float4*)s_lnrow)[t];
            float4 b = ((const float4*)(cbn + (size_t)k * DD))[t];
            float p = la.x * b.x + la.y * b.y + la.z * b.z + la.w * b.w;
            #pragma unroll
            for (int o = 16; o > 0; o >>= 1) p += __shfl_xor_sync(0xffffffffu, p, o);
            if ((t & 31) == 0) s_red[t >> 5] = p;
            __syncthreads();
            if (t == 0) {
                float d = s_red[0] + s_red[1] + s_red[2] + s_red[3];
                if (d > bestv || (d == bestv && k < besti)) { bestv = d; besti = k; }
            }
            __syncthreads();
        }
        if (t == 0) s_arg = besti;
        __syncthreads();
        arg = s_arg;
    }

    float lsum = 0.0f;
    #pragma unroll
    for (int j = 0; j < 8; j++) {
        v[j] = expf(ALPHA * (v[j] - rowmax));
        lsum += v[j];
    }
    // warp shfl sum reduce
    #pragma unroll
    for (int o = 16; o > 0; o >>= 1) lsum += __shfl_xor_sync(0xffffffffu, lsum, o);
    __shared__ float sws[4];
    if ((t & 31) == 0) sws[t >> 5] = lsum;
    __syncthreads();
    float inv = 1.0f / (sws[0] + sws[1] + sws[2] + sws[3]);

    size_t rb = (size_t)row * KC + t * 8;
    float p0 = v[0] * inv, p1 = v[1] * inv, p2 = v[2] * inv, p3 = v[3] * inv;
    float p4 = v[4] * inv, p5 = v[5] * inv, p6 = v[6] * inv, p7 = v[7] * inv;
    float* sr = sa + rb;
    *(float2*)(sr + 0) = make_float2(p0, p1);
    *(float2*)(sr + 2) = make_float2(p2, p3);
    *(float2*)(sr + 4) = make_float2(p4, p5);
    *(float2*)(sr + 6) = make_float2(p6, p7);
    uint4 hu;
    *(__half2*)&hu.x = __floats2half2_rn(p0, p1);
    *(__half2*)&hu.y = __floats2half2_rn(p2, p3);
    *(__half2*)&hu.z = __floats2half2_rn(p4, p5);
    *(__half2*)&hu.w = __floats2half2_rn(p6, p7);
    ((uint4*)(g_sah + rb))[0] = hu;

    if (t == 0) {
        argm_out[row] = (float)arg;
        g_rowmax[row] = rowmax;
    }
    // hard_quantized[row,:] = W[arg,:]  (8B-aligned -> float2)
    const float2* wr = (const float2*)(W + (size_t)arg * DD);
    float2* hq = (float2*)(hardq + (size_t)row * DD);
    hq[2 * t + 0] = wr[2 * t + 0];
    hq[2 * t + 1] = wr[2 * t + 1];
}

// ---------------------------------------------------------------------------
// Column sums of soft_assign (reads fp16 copy). grid (KC/256, BSZ/1024).
__global__ __launch_bounds__(256) void colsum_kernel()
{
    int k = blockIdx.x * 256 + threadIdx.x;
    int r0 = blockIdx.y * 1024;
    float s = 0.0f;
    for (int r = 0; r < 1024; r++)
        s += __half2float(g_sah[(size_t)(r0 + r) * KC + k]);
    atomicAdd(&g_avg[k], s);
}

// ---------------------------------------------------------------------------
// Final scalars: vq_loss (from fused mse), entropy_vq, cluster_metric (rowmax).
__global__ __launch_bounds__(1024) void finalize_kernel(float* __restrict__ out)
{
    int t = threadIdx.x;
    float p = g_avg[t] * (1.0f / (float)BSZ);
    float ent = p * logf(p + 1e-10f);
    float rmx = 0.0f;
    #pragma unroll
    for (int j = 0; j < 16; j++) rmx += g_rowmax[t + j * 1024];
    __shared__ float se[1024];
    __shared__ float sr[1024];
    se[t] = ent; sr[t] = rmx;
    __syncthreads();
    #pragma unroll
    for (int s = 512; s > 0; s >>= 1) {
        if (t < s) { se[t] += se[t + s]; sr[t] += sr[t + s]; }
        __syncthreads();
    }
    if (t == 0) {
        double mse = g_mse_sum / (double)((size_t)BSZ * DD);
        out[OFF_VQ]  = (float)((1.0 + (double)BETA) * mse);
        out[OFF_ENT] = -se[0];
        out[OFF_CM]  = (float)((double)sr[0] / (double)BSZ);
    }
}

// ---------------------------------------------------------------------------
extern "C" void kernel_launch(void* const* d_in, const int* in_sizes, int n_in,
                              void* d_out, int out_size)
{
    const float* latents = (const float*)d_in[0];   // [B, D]
    const float* emb     = (const float*)d_in[1];   // [K, D]
    float* out = (float*)d_out;

    float* cbn = 0; cudaGetSymbolAddress((void**)&cbn, g_cbn);
    __half *atth = 0, *lnh = 0, *cbh = 0, *sah = 0, *wth = 0;
    cudaGetSymbolAddress((void**)&atth, g_atth);
    cudaGetSymbolAddress((void**)&lnh, g_lnh);
    cudaGetSymbolAddress((void**)&cbh, g_cbh);
    cudaGetSymbolAddress((void**)&sah, g_sah);
    cudaGetSymbolAddress((void**)&wth, g_wth);

    cudaFuncSetAttribute((const void*)hmma_gemm_kernel<true, false>,
                         cudaFuncAttributeMaxDynamicSharedMemorySize, GSMEM);
    cudaFuncSetAttribute((const void*)hmma_gemm_kernel<false, true>,
                         cudaFuncAttributeMaxDynamicSharedMemorySize, GSMEM);

    // Side stream + events for fork/join (host objects, created once; legal
    // under graph capture via event-based fork from the capture stream).
    static cudaStream_t s2 = 0;
    static cudaEvent_t evFork = 0, evPrep = 0, evFork2 = 0, evCol = 0;
    if (!s2) {
        cudaStreamCreateWithFlags(&s2, cudaStreamNonBlocking);
        cudaEventCreateWithFlags(&evFork,  cudaEventDisableTiming);
        cudaEventCreateWithFlags(&evPrep,  cudaEventDisableTiming);
        cudaEventCreateWithFlags(&evFork2, cudaEventDisableTiming);
        cudaEventCreateWithFlags(&evCol,   cudaEventDisableTiming);
    }

    float* q_out   = out + OFF_Q;
    float* arg_out = out + OFF_ARG;
    float* hq_out  = out + OFF_HQ;
    float* sa_out  = out + OFF_SA;

    init_kernel<<<1, 1024>>>();

    // fork: codebook-side prep on s2, latents l2norm on main
    cudaEventRecord(evFork, 0);
    cudaStreamWaitEvent(s2, evFork, 0);
    l2norm_kernel<true><<<KC, 128, 0, s2>>>(emb, cbn, cbh);
    {
        dim3 grid(KC / 32, DD / 32);
        transpose_h_kernel<<<grid, 1024, 0, s2>>>(emb, wth);
    }
    cudaEventRecord(evPrep, s2);

    l2norm_kernel<false><<<BSZ, 128>>>(latents, 0, lnh);

    // join: GEMM1 needs cbh (s2) + lnh (main)
    cudaStreamWaitEvent(0, evPrep, 0);

    // attention = ln [B,512] * cbn [1024,512]^T  (fp16 in/out, fp32 acc)
    {
        dim3 grid(KC / 128, BSZ / 128);
        hmma_gemm_kernel<true, false><<<grid, GTHREADS, GSMEM>>>(
            lnh, cbh, atth, 0, KC, DD);
    }

    softmax_kernel<<<BSZ, 128>>>(atth, emb, latents, cbn, sa_out, arg_out, hq_out);

    // fork: colsum (reads sah) on s2 concurrent with GEMM2 (also reads sah)
    cudaEventRecord(evFork2, 0);
    cudaStreamWaitEvent(s2, evFork2, 0);
    {
        dim3 grid(KC / 256, BSZ / 1024);
        colsum_kernel<<<grid, 256, 0, s2>>>();
    }
    cudaEventRecord(evCol, s2);

    // quantized = sa [B,1024] * Wt [512,1024]^T  (fp16, fp32 acc, fused MSE vs lnh)
    {
        dim3 grid(DD / 128, BSZ / 128);
        hmma_gemm_kernel<false, true><<<grid, GTHREADS, GSMEM>>>(
            sah, wth, q_out, lnh, DD, KC);
    }

    // join: finalize needs colsum (s2) + mse (main)
    cudaStreamWaitEvent(0, evCol, 0);
    finalize_kernel<<<1, 1024>>>(out);
}